// round 15
// baseline (speedup 1.0000x reference)
#include <cuda_runtime.h>
#include <cuda_bf16.h>
#include <cstdint>

#define SIGM(x) (1.f/(1.f+__expf(-(x))))

// ---------------- device scratch ----------------
__device__ float d_hU1[128*256];
__device__ float d_hU [128*256];
__device__ float d_giUf[128*1536];
__device__ float d_giUb[128*1536];
__device__ float d_stF[800*512];
__device__ float d_stB[800*512];
__device__ float d_ghF[800*1536];
__device__ float d_ghB[800*1536];
__device__ float d_gdf[39321600ll];      // (t*32+b) x 1536
__device__ float d_gdr[39321600ll];
__device__ unsigned d_histHL[2*801*16384ll]; // packed bf16 (hi | lo<<16), [dec][t][b*512+j]
__device__ float    d_histF [2*801*16384ll]; // fp32 h,                   [dec][t][b*512+j]
__device__ float d_uf[1536], d_vf[1536], d_ur[1536], d_vr[1536];
__device__ unsigned g_cnt;

// bf16 hi/lo planes
__device__ __nv_bfloat16 d_WefH[786432],  d_WefL[786432];   // encf Whh 1536x512
__device__ __nv_bfloat16 d_WebH[786432],  d_WebL[786432];
__device__ __nv_bfloat16 d_WdfH[1572864], d_WdfL[1572864];  // dec Wih[:, :1024] 1536x1024
__device__ __nv_bfloat16 d_WdrH[1572864], d_WdrL[1572864];
__device__ __nv_bfloat16 d_WhfH[786432],  d_WhfL[786432];   // decf Whh 1536x512
__device__ __nv_bfloat16 d_WhrH[786432],  d_WhrL[786432];   // decr Whh
__device__ __nv_bfloat16 d_stFH[409600],  d_stFL[409600];   // 800x512
__device__ __nv_bfloat16 d_stBH[409600],  d_stBL[409600];
__device__ __nv_bfloat16 d_encH[26214400ll], d_encL[26214400ll]; // 25600x1024

// ---------------- helpers ----------------
__device__ __forceinline__ uint32_t smem_u32(const void* p) {
    uint32_t a;
    asm("{ .reg .u64 t; cvta.to.shared.u64 t, %1; cvt.u32.u64 %0, t; }" : "=r"(a) : "l"(p));
    return a;
}
__device__ __forceinline__ void ldsm4(uint32_t& r0, uint32_t& r1, uint32_t& r2, uint32_t& r3,
                                      uint32_t addr) {
    asm volatile("ldmatrix.sync.aligned.m8n8.x4.shared.b16 {%0,%1,%2,%3}, [%4];"
                 : "=r"(r0), "=r"(r1), "=r"(r2), "=r"(r3) : "r"(addr));
}
__device__ __forceinline__ void ldsm2(uint32_t& r0, uint32_t& r1, uint32_t addr) {
    asm volatile("ldmatrix.sync.aligned.m8n8.x2.shared.b16 {%0,%1}, [%2];"
                 : "=r"(r0), "=r"(r1) : "r"(addr));
}
__device__ __forceinline__ void mma16816(float* c, const uint32_t* a, uint32_t b0, uint32_t b1) {
    asm volatile("mma.sync.aligned.m16n8k16.row.col.f32.bf16.bf16.f32 "
        "{%0,%1,%2,%3},{%4,%5,%6,%7},{%8,%9},{%0,%1,%2,%3};"
        : "+f"(c[0]), "+f"(c[1]), "+f"(c[2]), "+f"(c[3])
        : "r"(a[0]), "r"(a[1]), "r"(a[2]), "r"(a[3]), "r"(b0), "r"(b1));
}
__device__ __forceinline__ void cp_async16(uint32_t dst, const void* src, int szn) {
    asm volatile("cp.async.cg.shared.global [%0], [%1], 16, %2;"
                 :: "r"(dst), "l"(src), "r"(szn) : "memory");
}
#define CP_COMMIT() asm volatile("cp.async.commit_group;" ::: "memory")
#define CP_WAIT1()  asm volatile("cp.async.wait_group 1;" ::: "memory")
#define CP_WAIT0()  asm volatile("cp.async.wait_group 0;" ::: "memory")

// ---------------- init ----------------
__global__ void init_k() {
    int i = blockIdx.x*256 + threadIdx.x;   // 409600 threads
    d_stF[i] = 0.f; d_stB[i] = 0.f;
    __nv_bfloat16 z = __float2bfloat16(0.f);
    d_stFH[i] = z; d_stFL[i] = z; d_stBH[i] = z; d_stBL[i] = z;
    if (i < 16384) {
        d_histHL[i] = 0u; d_histHL[801*16384ll + i] = 0u;
        d_histF [i] = 0.f; d_histF [801*16384ll + i] = 0.f;
    }
    if (i == 0) g_cnt = 0u;
}

// ---------------- fp32 -> bf16 hi/lo ----------------
__global__ void cvt_k(const float* __restrict__ src, int srcld, int K,
                      __nv_bfloat16* __restrict__ hi, __nv_bfloat16* __restrict__ lo,
                      int total) {
    int i = blockIdx.x*256 + threadIdx.x;
    if (i >= total) return;
    int r = i / K, c = i % K;
    float v = src[(size_t)r*srcld + c];
    __nv_bfloat16 h = __float2bfloat16(v);
    hi[i] = h;
    lo[i] = __float2bfloat16(v - __bfloat162float(h));
}

// ---------------- bf16-split tensor GEMM, cp.async double-buffered ----------
// A hi/lo [M,K], B hi/lo [N,K]. tile 128M x 128N, k-chunk 32, 2-stage pipeline.
// dyn smem: sA[2][2][128][40] @0 (40960B), sB same @40960. total 81920B.
__global__ __launch_bounds__(256) void tgemm_k(
    const __nv_bfloat16* __restrict__ AH0, const __nv_bfloat16* __restrict__ AL0,
    const __nv_bfloat16* __restrict__ AH1, const __nv_bfloat16* __restrict__ AL1,
    const __nv_bfloat16* __restrict__ BH0, const __nv_bfloat16* __restrict__ BL0,
    const __nv_bfloat16* __restrict__ BH1, const __nv_bfloat16* __restrict__ BL1,
    const float* __restrict__ bias0, const float* __restrict__ bias1,
    float* __restrict__ C0, float* __restrict__ C1,
    int ldc, int M, int K)
{
    extern __shared__ char dyn[];
    __nv_bfloat16* sA = (__nv_bfloat16*)dyn;             // [buf][pl][128][40]
    __nv_bfloat16* sB = (__nv_bfloat16*)(dyn + 40960);
    int tid = threadIdx.x, w = tid >> 5, ln = tid & 31;
    int z = blockIdx.z;
    const __nv_bfloat16* AH = z ? AH1 : AH0;
    const __nv_bfloat16* AL = z ? AL1 : AL0;
    const __nv_bfloat16* BH = z ? BH1 : BH0;
    const __nv_bfloat16* BL = z ? BL1 : BL0;
    const float* bias = z ? bias1 : bias0;
    float* C = z ? C1 : C0;
    int m0 = blockIdx.y*128, n0 = blockIdx.x*128;
    int mw = (w >> 2)*64, nw = (w & 3)*32;

    float acc[4][4][4];
#pragma unroll
    for (int a = 0; a < 4; a++)
#pragma unroll
        for (int b = 0; b < 4; b++)
#pragma unroll
            for (int c = 0; c < 4; c++) acc[a][b][c] = 0.f;

    uint32_t saB = smem_u32(sA), sbB = smem_u32(sB);
    int g = ln >> 3, lr = ln & 7;
    int aRow = (g & 1)*8 + lr, aK = (g >> 1)*8;
    int bRow = (g >> 1)*8 + lr, bK = (g & 1)*8;

    // per-thread load slots: 8 x 16B each (2048 total)
    int nchunk = K / 32;
    auto issue = [&](int c, int buf) {
#pragma unroll
        for (int l = 0; l < 8; l++) {
            int i = tid + l*256;
            int pl = i >> 9, r = (i >> 2) & 127, u = i & 3;
            if (pl < 2) {
                int gm = m0 + r;
                const __nv_bfloat16* s = (pl ? AL : AH) + (size_t)gm*K + c*32 + u*8;
                uint32_t d = saB + (uint32_t)(buf*20480 + pl*10240 + (r*40 + u*8)*2);
                cp_async16(d, s, (gm < M) ? 16 : 0);
            } else {
                const __nv_bfloat16* s = ((pl & 1) ? BL : BH) + (size_t)(n0 + r)*K + c*32 + u*8;
                uint32_t d = sbB + (uint32_t)(buf*20480 + (pl & 1)*10240 + (r*40 + u*8)*2);
                cp_async16(d, s, 16);
            }
        }
    };

    issue(0, 0);
    CP_COMMIT();
    for (int c = 0; c < nchunk; c++) {
        int buf = c & 1;
        if (c + 1 < nchunk) {
            issue(c + 1, buf ^ 1);
            CP_COMMIT();
            CP_WAIT1();
        } else {
            CP_WAIT0();
        }
        __syncthreads();
        uint32_t a0 = saB + buf*20480, a1 = a0 + 10240;
        uint32_t b0 = sbB + buf*20480, b1 = b0 + 10240;
#pragma unroll
        for (int kk = 0; kk < 32; kk += 16) {
            uint32_t ah[4][4], al[4][4], bh[2][4], bl[2][4];
#pragma unroll
            for (int mt = 0; mt < 4; mt++) {
                uint32_t off = (uint32_t)(((mw + mt*16 + aRow)*40 + kk + aK)*2);
                ldsm4(ah[mt][0], ah[mt][1], ah[mt][2], ah[mt][3], a0 + off);
                ldsm4(al[mt][0], al[mt][1], al[mt][2], al[mt][3], a1 + off);
            }
#pragma unroll
            for (int np = 0; np < 2; np++) {
                uint32_t off = (uint32_t)(((nw + np*16 + bRow)*40 + kk + bK)*2);
                ldsm4(bh[np][0], bh[np][1], bh[np][2], bh[np][3], b0 + off);
                ldsm4(bl[np][0], bl[np][1], bl[np][2], bl[np][3], b1 + off);
            }
#pragma unroll
            for (int mt = 0; mt < 4; mt++)
#pragma unroll
                for (int nt = 0; nt < 4; nt++) {
                    int np = nt >> 1, half = (nt & 1)*2;
                    mma16816(acc[mt][nt], ah[mt], bh[np][half], bh[np][half+1]);
                    mma16816(acc[mt][nt], ah[mt], bl[np][half], bl[np][half+1]);
                    mma16816(acc[mt][nt], al[mt], bh[np][half], bh[np][half+1]);
                }
        }
        __syncthreads();
    }
    int cr = ln >> 2, cc = (ln & 3)*2;
#pragma unroll
    for (int mt = 0; mt < 4; mt++) {
#pragma unroll
        for (int nt = 0; nt < 4; nt++) {
            int row = m0 + mw + mt*16 + cr;
            int col = n0 + nw + nt*8 + cc;
            float b0 = bias ? bias[col] : 0.f, b1 = bias ? bias[col+1] : 0.f;
            if (row < M) {
                float2 o; o.x = acc[mt][nt][0] + b0; o.y = acc[mt][nt][1] + b1;
                *(float2*)(C + (size_t)row*ldc + col) = o;
            }
            if (row + 8 < M) {
                float2 o; o.x = acc[mt][nt][2] + b0; o.y = acc[mt][nt][3] + b1;
                *(float2*)(C + (size_t)(row+8)*ldc + col) = o;
            }
        }
    }
}

// ---------------- small fp32 SGEMM (prenet / giU only) ----------------
__global__ __launch_bounds__(256) void sgemm_k(
    const float* __restrict__ A, int lda, const float* __restrict__ W, int ldw,
    const float* __restrict__ bias, float* __restrict__ C, int ldc,
    int M, int K, int act)
{
    __shared__ float As[16][132];
    __shared__ float Bs[16][68];
    int tid = threadIdx.x;
    int m0 = blockIdx.y*128, n0 = blockIdx.x*64;
    int tn = tid & 15, tmi = tid >> 4;
    float acc[8][4];
#pragma unroll
    for (int i = 0; i < 8; i++)
#pragma unroll
        for (int j = 0; j < 4; j++) acc[i][j] = 0.f;
    for (int k0 = 0; k0 < K; k0 += 16) {
#pragma unroll
        for (int l = 0; l < 2; l++) {
            int idx = tid + l*256;
            int m = idx >> 2, kq = (idx & 3)*4;
            float4 v = make_float4(0.f,0.f,0.f,0.f);
            if (m0 + m < M) v = *(const float4*)(A + (size_t)(m0+m)*lda + k0 + kq);
            As[kq][m]=v.x; As[kq+1][m]=v.y; As[kq+2][m]=v.z; As[kq+3][m]=v.w;
        }
        {
            int n = tid >> 2, kq = (tid & 3)*4;
            float4 v = *(const float4*)(W + (size_t)(n0+n)*ldw + k0 + kq);
            Bs[kq][n]=v.x; Bs[kq+1][n]=v.y; Bs[kq+2][n]=v.z; Bs[kq+3][n]=v.w;
        }
        __syncthreads();
#pragma unroll
        for (int k = 0; k < 16; k++) {
            float a[8], bb[4];
#pragma unroll
            for (int i = 0; i < 8; i++) a[i] = As[k][tmi*8+i];
#pragma unroll
            for (int j = 0; j < 4; j++) bb[j] = Bs[k][tn*4+j];
#pragma unroll
            for (int i = 0; i < 8; i++)
#pragma unroll
                for (int j = 0; j < 4; j++) acc[i][j] += a[i]*bb[j];
        }
        __syncthreads();
    }
    float bv[4] = {0.f,0.f,0.f,0.f};
    if (bias) {
#pragma unroll
        for (int j = 0; j < 4; j++) bv[j] = bias[n0 + tn*4 + j];
    }
#pragma unroll
    for (int i = 0; i < 8; i++) {
        int gm = m0 + tmi*8 + i;
        if (gm < M) {
            float4 o;
            o.x = acc[i][0]+bv[0]; o.y = acc[i][1]+bv[1];
            o.z = acc[i][2]+bv[2]; o.w = acc[i][3]+bv[3];
            if (act) { o.x=tanhf(o.x); o.y=tanhf(o.y); o.z=tanhf(o.z); o.w=tanhf(o.w); }
            *(float4*)(C + (size_t)gm*ldc + n0 + tn*4) = o;
        }
    }
}

// ---------------- encoder gate, step s, both dirs ----------------
__global__ void enc_gate_k(int s, const int* __restrict__ note) {
    int idx = blockIdx.x*256 + threadIdx.x;   // t*512+j
    int dir = blockIdx.z;
    int t = idx >> 9, j = idx & 511;
    int b = dir ? 31 - s : s;
    const float* giU = dir ? d_giUb : d_giUf;
    const float* gh  = dir ? d_ghB  : d_ghF;
    float* st        = dir ? d_stB  : d_stF;
    __nv_bfloat16* sh = dir ? d_stBH : d_stFH;
    __nv_bfloat16* sl = dir ? d_stBL : d_stFL;
    int nid = note[b*800 + t] & 127;
    const float* gi = giU + (size_t)nid*1536;
    const float* g  = gh + (size_t)t*1536;
    float ir = gi[j], iz = gi[512+j], in = gi[1024+j];
    float hr = g[j],  hz = g[512+j],  hn = g[1024+j];
    float h  = st[t*512 + j];
    float r = SIGM(ir+hr), z = SIGM(iz+hz);
    float nn = tanhf(in + r*hn);
    float hnew = (1.f - z)*nn + z*h;
    st[t*512 + j] = hnew;
    __nv_bfloat16 hb = __float2bfloat16(hnew);
    __nv_bfloat16 lb = __float2bfloat16(hnew - __bfloat162float(hb));
    sh[t*512 + j] = hb; sl[t*512 + j] = lb;
    size_t eo = ((size_t)t*32 + b)*1024 + dir*512 + j;
    d_encH[eo] = hb; d_encL[eo] = lb;
}

// ---------------- fold 64-dim prev embedding into dec gi ----------------
__global__ void uv_k(const float* __restrict__ fWih, const float* __restrict__ fW,
                     const float* __restrict__ fb,   const float* __restrict__ fbih,
                     const float* __restrict__ rWih, const float* __restrict__ rW,
                     const float* __restrict__ rb,   const float* __restrict__ rbih) {
    int i = blockIdx.x*256 + threadIdx.x;
    if (i >= 3072) return;
    int dec = i / 1536, j = i % 1536;
    const float* row = (dec ? rWih : fWih) + (size_t)j*1088 + 1024;
    const float* ew = dec ? rW : fW;
    const float* eb = dec ? rb : fb;
    float u = 0.f, v = 0.f;
#pragma unroll 8
    for (int c = 0; c < 64; c++) { u += ew[c]*row[c]; v += eb[c]*row[c]; }
    v += (dec ? rbih : fbih)[j];
    if (dec) { d_ur[j] = u; d_vr[j] = v; } else { d_uf[j] = u; d_vf[j] = v; }
}

// ---------------- persistent dual-decoder, 800 steps, tensor-core gh --------
// 128 blocks, 1/SM. Block = (dec = bb>>6, kb = (bb&63)*8). R12 barrier
// (monotonic global counter) — measured best of three variants.
__global__ __launch_bounds__(256, 1) void dec_k(
    const float* __restrict__ fbhh, const float* __restrict__ rbhh,
    const float* __restrict__ f0p,  const float* __restrict__ rmp)
{
    extern __shared__ char smc[];
    __nv_bfloat16* Whi = (__nv_bfloat16*)smc;     // [32][520]
    __nv_bfloat16* Wlo = Whi + 32*520;
    __nv_bfloat16* hHi = Wlo + 32*520;
    __nv_bfloat16* hLo = hHi + 32*520;
    float* ghs = (float*)(hLo + 32*520);          // [2][24][33]
    float* cb  = ghs + 2*24*33;                   // [72]

    int tid = threadIdx.x, bb = blockIdx.x;
    int w = tid >> 5, ln = tid & 31;
    int dec = bb >> 6, kb = (bb & 63)*8;
    const float* bhh = dec ? rbhh : fbhh;
    const float* gi  = dec ? d_gdr : d_gdf;
    const float* prv = dec ? rmp  : f0p;
    const __nv_bfloat16* WH = dec ? d_WhrH : d_WhfH;
    const __nv_bfloat16* WL = dec ? d_WhrL : d_WhfL;
    unsigned* histHL = d_histHL + (size_t)dec*(801*16384ll);
    float*    histF  = d_histF  + (size_t)dec*(801*16384ll);

    for (int i = tid; i < 1536; i += 256) {
        int row = i >> 6, c8 = i & 63;
        int j = (row >> 3)*512 + kb + (row & 7);
        *(uint4*)(Whi + row*520 + c8*8) = ((const uint4*)(WH + (size_t)j*512))[c8];
        *(uint4*)(Wlo + row*520 + c8*8) = ((const uint4*)(WL + (size_t)j*512))[c8];
    }
    for (int i = tid; i < 520; i += 256) {
        int row = 24 + i/65, c8 = i%65;
        *(uint4*)(Whi + row*520 + c8*8) = make_uint4(0,0,0,0);
        *(uint4*)(Wlo + row*520 + c8*8) = make_uint4(0,0,0,0);
    }
    if (tid < 24) {
        int jj = (tid >> 3)*512 + kb + (tid & 7);
        cb[tid]    = bhh[jj];
        cb[24+tid] = (dec ? d_ur : d_uf)[jj];
        cb[48+tid] = (dec ? d_vr : d_vf)[jj];
    }
    __syncthreads();

    uint32_t sWhi = smem_u32(Whi), sWlo = smem_u32(Wlo);
    uint32_t sHhi = smem_u32(hHi), sHlo = smem_u32(hLo);

    int mt = w & 1, np = (w >> 1) & 1, ks = w >> 2;
    int g = ln >> 3, lr = ln & 7;
    int aRow = (g & 1)*8 + lr, aK = (g >> 1)*8;
    int l4 = ln & 15;
    int bR = l4 & 7, bT = (l4 >> 3)*8;

    int gb = tid >> 3, gj = tid & 7;       // gate-phase (b, j)
    float b0c = cb[gj],    b1c = cb[8+gj],  b2c = cb[16+gj];
    float u0  = cb[24+gj], u1  = cb[32+gj], u2  = cb[40+gj];
    float v0  = cb[48+gj], v1  = cb[56+gj], v2  = cb[64+gj];
    float hold = 0.f;
    const float* prow = prv + gb*800;

    for (int t = 0; t < 800; t++) {
        size_t gbase = ((size_t)t*32 + gb)*1536 + kb + gj;
        float gir = gi[gbase], giz = gi[gbase+512], gin = gi[gbase+1024];
        float f = prow[t];
        const uint4* src = (const uint4*)(histHL + (size_t)t*16384);
        for (int i = tid; i < 4096; i += 256) {
            uint4 v = src[i];
            int b = i >> 7, j4 = (i & 127)*4;
            uint32_t h01 = (v.x & 0xffffu) | (v.y << 16);
            uint32_t h23 = (v.z & 0xffffu) | (v.w << 16);
            uint32_t l01 = (v.x >> 16) | (v.y & 0xffff0000u);
            uint32_t l23 = (v.z >> 16) | (v.w & 0xffff0000u);
            *(uint2*)(hHi + b*520 + j4) = make_uint2(h01, h23);
            *(uint2*)(hLo + b*520 + j4) = make_uint2(l01, l23);
        }
        __syncthreads();
        float c0[4] = {0.f,0.f,0.f,0.f}, c1[4] = {0.f,0.f,0.f,0.f};
#pragma unroll 4
        for (int k = 0; k < 16; k++) {
            int kk = (ks*16 + k)*16;
            uint32_t offA = (uint32_t)(((mt*16 + aRow)*520 + kk + aK)*2);
            uint32_t ah[4], al[4];
            ldsm4(ah[0],ah[1],ah[2],ah[3], sWhi + offA);
            ldsm4(al[0],al[1],al[2],al[3], sWlo + offA);
#pragma unroll
            for (int i2 = 0; i2 < 2; i2++) {
                int nbase = np*16 + i2*8;
                uint32_t offB = (uint32_t)(((nbase + bR)*520 + kk + bT)*2);
                uint32_t bh0,bh1,bl0,bl1;
                ldsm2(bh0,bh1, sHhi + offB);
                ldsm2(bl0,bl1, sHlo + offB);
                float* cc = i2 ? c1 : c0;
                mma16816(cc, ah, bh0, bh1);
                mma16816(cc, ah, bl0, bl1);
                mma16816(cc, al, bh0, bh1);
            }
        }
        {
            int row = mt*16 + (ln >> 2);
            int col = 2*(ln & 3);
            float* g0 = ghs + ks*(24*33);
#pragma unroll
            for (int i2 = 0; i2 < 2; i2++) {
                float* cc = i2 ? c1 : c0;
                int bcol = np*16 + i2*8 + col;
                g0[row*33 + bcol]     = cc[0];
                g0[row*33 + bcol + 1] = cc[1];
                if (mt == 0) {
                    g0[(row+8)*33 + bcol]     = cc[2];
                    g0[(row+8)*33 + bcol + 1] = cc[3];
                }
            }
        }
        __syncthreads();
        {
            float a0 = ghs[gj*33 + gb]      + ghs[24*33 + gj*33 + gb];
            float a1 = ghs[(8+gj)*33 + gb]  + ghs[24*33 + (8+gj)*33 + gb];
            float a2 = ghs[(16+gj)*33 + gb] + ghs[24*33 + (16+gj)*33 + gb];
            float ir = gir + f*u0 + v0;
            float iz = giz + f*u1 + v1;
            float in = gin + f*u2 + v2;
            float r = SIGM(ir + a0 + b0c);
            float z = SIGM(iz + a1 + b1c);
            float nn = tanhf(in + r*(a2 + b2c));
            float hnew = (1.f - z)*nn + z*hold;
            hold = hnew;
            __nv_bfloat16 hb = __float2bfloat16(hnew);
            __nv_bfloat16 lb = __float2bfloat16(hnew - __bfloat162float(hb));
            unsigned hu = *(unsigned short*)&hb;
            unsigned lu = *(unsigned short*)&lb;
            size_t o = (size_t)(t+1)*16384 + gb*512 + kb + gj;
            histHL[o] = hu | (lu << 16);
            histF[o]  = hnew;
        }
        if (t < 799) {
            __syncthreads();
            if (tid == 0) {
                __threadfence();
                atomicAdd(&g_cnt, 1u);
                unsigned target = 128u*(unsigned)(t+1);
                while (*(volatile unsigned*)&g_cnt < target) __nanosleep(32);
                __threadfence();
            }
            __syncthreads();
        }
    }
}

// ---------------- output projections ----------------
__global__ void out_k(const float* __restrict__ pfW, const float* __restrict__ pfb,
                      const float* __restrict__ prW, const float* __restrict__ prb,
                      float* __restrict__ out) {
    int t = blockIdx.x, dec = blockIdx.y, tid = threadIdx.x;
    int b = tid >> 3, seg = tid & 7;
    const float* W = dec ? prW : pfW;
    const float* h = d_histF + (size_t)dec*(801*16384ll) + (size_t)(t+1)*16384 + b*512 + seg*64;
    const float* Wp = W + seg*64;
    float s = 0.f;
#pragma unroll
    for (int jj = 0; jj < 64; jj += 4) {
        float4 hv = *(const float4*)(h + jj);
        float4 wv = *(const float4*)(Wp + jj);
        s += hv.x*wv.x + hv.y*wv.y + hv.z*wv.z + hv.w*wv.w;
    }
    s += __shfl_down_sync(0xffffffffu, s, 4);
    s += __shfl_down_sync(0xffffffffu, s, 2);
    s += __shfl_down_sync(0xffffffffu, s, 1);
    if (seg == 0) out[(size_t)dec*25600 + b*800 + t] = s + (dec ? prb[0] : pfb[0]);
}

// ---------------- host ----------------
extern "C" void kernel_launch(void* const* d_in, const int* in_sizes, int n_in,
                              void* d_out, int out_size) {
    const int*   note = (const int*)d_in[0];
    const float* f0p  = (const float*)d_in[1];
    const float* rmp  = (const float*)d_in[2];
    const float* nemb = (const float*)d_in[3];
    const float* f0W  = (const float*)d_in[4];
    const float* f0b  = (const float*)d_in[5];
    const float* rmW  = (const float*)d_in[6];
    const float* rmb  = (const float*)d_in[7];
    const float* p1W  = (const float*)d_in[8];
    const float* p1b  = (const float*)d_in[9];
    const float* p2W  = (const float*)d_in[10];
    const float* p2b  = (const float*)d_in[11];
    const float* efWih = (const float*)d_in[12];
    const float* efWhh = (const float*)d_in[13];
    const float* efbih = (const float*)d_in[14];
    const float* efbhh = (const float*)d_in[15];
    const float* ebWih = (const float*)d_in[16];
    const float* ebWhh = (const float*)d_in[17];
    const float* ebbih = (const float*)d_in[18];
    const float* ebbhh = (const float*)d_in[19];
    const float* dfWih = (const float*)d_in[20];
    const float* dfWhh = (const float*)d_in[21];
    const float* dfbih = (const float*)d_in[22];
    const float* dfbhh = (const float*)d_in[23];
    const float* drWih = (const float*)d_in[24];
    const float* drWhh = (const float*)d_in[25];
    const float* drbih = (const float*)d_in[26];
    const float* drbhh = (const float*)d_in[27];
    const float* pfW   = (const float*)d_in[28];
    const float* pfb   = (const float*)d_in[29];
    const float* prW   = (const float*)d_in[30];
    const float* prb   = (const float*)d_in[31];

    float *hU1, *hU, *giUf, *giUb, *stF, *stB, *ghF, *ghB, *gdf, *gdr;
    __nv_bfloat16 *WefH,*WefL,*WebH,*WebL,*WdfH,*WdfL,*WdrH,*WdrL;
    __nv_bfloat16 *WhfH,*WhfL,*WhrH,*WhrL;
    __nv_bfloat16 *stFH,*stFL,*stBH,*stBL,*encH,*encL;
    cudaGetSymbolAddress((void**)&hU1,  d_hU1);
    cudaGetSymbolAddress((void**)&hU,   d_hU);
    cudaGetSymbolAddress((void**)&giUf, d_giUf);
    cudaGetSymbolAddress((void**)&giUb, d_giUb);
    cudaGetSymbolAddress((void**)&stF,  d_stF);
    cudaGetSymbolAddress((void**)&stB,  d_stB);
    cudaGetSymbolAddress((void**)&ghF,  d_ghF);
    cudaGetSymbolAddress((void**)&ghB,  d_ghB);
    cudaGetSymbolAddress((void**)&gdf,  d_gdf);
    cudaGetSymbolAddress((void**)&gdr,  d_gdr);
    cudaGetSymbolAddress((void**)&WefH, d_WefH); cudaGetSymbolAddress((void**)&WefL, d_WefL);
    cudaGetSymbolAddress((void**)&WebH, d_WebH); cudaGetSymbolAddress((void**)&WebL, d_WebL);
    cudaGetSymbolAddress((void**)&WdfH, d_WdfH); cudaGetSymbolAddress((void**)&WdfL, d_WdfL);
    cudaGetSymbolAddress((void**)&WdrH, d_WdrH); cudaGetSymbolAddress((void**)&WdrL, d_WdrL);
    cudaGetSymbolAddress((void**)&WhfH, d_WhfH); cudaGetSymbolAddress((void**)&WhfL, d_WhfL);
    cudaGetSymbolAddress((void**)&WhrH, d_WhrH); cudaGetSymbolAddress((void**)&WhrL, d_WhrL);
    cudaGetSymbolAddress((void**)&stFH, d_stFH); cudaGetSymbolAddress((void**)&stFL, d_stFL);
    cudaGetSymbolAddress((void**)&stBH, d_stBH); cudaGetSymbolAddress((void**)&stBL, d_stBL);
    cudaGetSymbolAddress((void**)&encH, d_encH); cudaGetSymbolAddress((void**)&encL, d_encL);

    init_k<<<1600, 256>>>();

    // weight hi/lo conversions
    cvt_k<<<3072, 256>>>(efWhh, 512, 512, WefH, WefL, 786432);
    cvt_k<<<3072, 256>>>(ebWhh, 512, 512, WebH, WebL, 786432);
    cvt_k<<<6144, 256>>>(dfWih, 1088, 1024, WdfH, WdfL, 1572864);
    cvt_k<<<6144, 256>>>(drWih, 1088, 1024, WdrH, WdrL, 1572864);
    cvt_k<<<3072, 256>>>(dfWhh, 512, 512, WhfH, WhfL, 786432);
    cvt_k<<<3072, 256>>>(drWhh, 512, 512, WhrH, WhrL, 786432);

    // prenet + encoder input projections on 128 unique notes (fp32)
    sgemm_k<<<dim3(4,1), 256>>>(nemb, 256, p1W, 256, p1b, hU1, 256, 128, 256, 1);
    sgemm_k<<<dim3(4,1), 256>>>(hU1, 256, p2W, 256, p2b, hU,  256, 128, 256, 1);
    sgemm_k<<<dim3(24,1), 256>>>(hU, 256, efWih, 256, efbih, giUf, 1536, 128, 256, 0);
    sgemm_k<<<dim3(24,1), 256>>>(hU, 256, ebWih, 256, ebbih, giUb, 1536, 128, 256, 0);
    uv_k<<<12, 256>>>(dfWih, f0W, f0b, dfbih, drWih, rmW, rmb, drbih);

    int tg_smem = 81920;
    cudaFuncSetAttribute(tgemm_k, cudaFuncAttributeMaxDynamicSharedMemorySize, tg_smem);

    // encoder recurrence over B=32 steps (tensor, both dirs fused)
    for (int s = 0; s < 32; s++) {
        tgemm_k<<<dim3(12,7,2), 256, tg_smem>>>(
            stFH, stFL, stBH, stBL,
            WefH, WefL, WebH, WebL,
            efbhh, ebbhh, ghF, ghB, 1536, 800, 512);
        enc_gate_k<<<dim3(1600,1,2), 256>>>(s, note);
    }

    // decoder input projections (tensor, both decs fused)
    tgemm_k<<<dim3(12,200,2), 256, tg_smem>>>(
        encH, encL, encH, encL,
        WdfH, WdfL, WdrH, WdrL,
        nullptr, nullptr, gdf, gdr, 1536, 25600, 1024);

    // persistent dual decoder (tensor-core recurrence)
    int smem = 4*(32*520)*2 + (2*24*33 + 72)*4;   // 139744 B
    cudaFuncSetAttribute(dec_k, cudaFuncAttributeMaxDynamicSharedMemorySize, smem);
    dec_k<<<128, 256, smem>>>(dfbhh, drbhh, f0p, rmp);

    out_k<<<dim3(800,2), 256>>>(pfW, pfb, prW, prb, (float*)d_out);
}

// round 17
// speedup vs baseline: 1.2081x; 1.2081x over previous
#include <cuda_runtime.h>
#include <cuda_bf16.h>
#include <cstdint>

#define SIGM(x) (1.f/(1.f+__expf(-(x))))

// ---------------- device scratch ----------------
__device__ float d_hU1[128*256];
__device__ float d_hU [128*256];
__device__ float d_giUf[128*1536];
__device__ float d_giUb[128*1536];
__device__ float d_stF[800*512];
__device__ float d_stB[800*512];
__device__ float d_ghF[800*1536];
__device__ float d_ghB[800*1536];
__device__ float d_gdf[39321600ll];      // (t*32+b) x 1536
__device__ float d_gdr[39321600ll];
__device__ unsigned d_histHL[2*801*16384ll]; // packed bf16 (hi | lo<<16), [dec][t][b*512+j]
__device__ float    d_histF [2*801*16384ll]; // fp32 h,                   [dec][t][b*512+j]
__device__ float d_uf[1536], d_vf[1536], d_ur[1536], d_vr[1536];
__device__ unsigned g_cnt2[64];   // per-decoder counters at [0] and [32] (128B apart)

// bf16 hi/lo planes
__device__ __nv_bfloat16 d_WefH[786432],  d_WefL[786432];   // encf Whh 1536x512
__device__ __nv_bfloat16 d_WebH[786432],  d_WebL[786432];
__device__ __nv_bfloat16 d_WdfH[1572864], d_WdfL[1572864];  // dec Wih[:, :1024] 1536x1024
__device__ __nv_bfloat16 d_WdrH[1572864], d_WdrL[1572864];
__device__ __nv_bfloat16 d_WhfH[786432],  d_WhfL[786432];   // decf Whh 1536x512
__device__ __nv_bfloat16 d_WhrH[786432],  d_WhrL[786432];   // decr Whh
__device__ __nv_bfloat16 d_stFH[409600],  d_stFL[409600];   // 800x512
__device__ __nv_bfloat16 d_stBH[409600],  d_stBL[409600];
__device__ __nv_bfloat16 d_encH[26214400ll], d_encL[26214400ll]; // 25600x1024

// ---------------- helpers ----------------
__device__ __forceinline__ uint32_t smem_u32(const void* p) {
    uint32_t a;
    asm("{ .reg .u64 t; cvta.to.shared.u64 t, %1; cvt.u32.u64 %0, t; }" : "=r"(a) : "l"(p));
    return a;
}
__device__ __forceinline__ void ldsm4(uint32_t& r0, uint32_t& r1, uint32_t& r2, uint32_t& r3,
                                      uint32_t addr) {
    asm volatile("ldmatrix.sync.aligned.m8n8.x4.shared.b16 {%0,%1,%2,%3}, [%4];"
                 : "=r"(r0), "=r"(r1), "=r"(r2), "=r"(r3) : "r"(addr));
}
__device__ __forceinline__ void ldsm2(uint32_t& r0, uint32_t& r1, uint32_t addr) {
    asm volatile("ldmatrix.sync.aligned.m8n8.x2.shared.b16 {%0,%1}, [%2];"
                 : "=r"(r0), "=r"(r1) : "r"(addr));
}
__device__ __forceinline__ void mma16816(float* c, const uint32_t* a, uint32_t b0, uint32_t b1) {
    asm volatile("mma.sync.aligned.m16n8k16.row.col.f32.bf16.bf16.f32 "
        "{%0,%1,%2,%3},{%4,%5,%6,%7},{%8,%9},{%0,%1,%2,%3};"
        : "+f"(c[0]), "+f"(c[1]), "+f"(c[2]), "+f"(c[3])
        : "r"(a[0]), "r"(a[1]), "r"(a[2]), "r"(a[3]), "r"(b0), "r"(b1));
}

// ---------------- init ----------------
__global__ void init_k() {
    int i = blockIdx.x*256 + threadIdx.x;   // 409600 threads
    d_stF[i] = 0.f; d_stB[i] = 0.f;
    __nv_bfloat16 z = __float2bfloat16(0.f);
    d_stFH[i] = z; d_stFL[i] = z; d_stBH[i] = z; d_stBL[i] = z;
    if (i < 16384) {
        d_histHL[i] = 0u; d_histHL[801*16384ll + i] = 0u;
        d_histF [i] = 0.f; d_histF [801*16384ll + i] = 0.f;
    }
    if (i < 64) g_cnt2[i] = 0u;
}

// ---------------- fp32 -> bf16 hi/lo ----------------
__global__ void cvt_k(const float* __restrict__ src, int srcld, int K,
                      __nv_bfloat16* __restrict__ hi, __nv_bfloat16* __restrict__ lo,
                      int total) {
    int i = blockIdx.x*256 + threadIdx.x;
    if (i >= total) return;
    int r = i / K, c = i % K;
    float v = src[(size_t)r*srcld + c];
    __nv_bfloat16 h = __float2bfloat16(v);
    hi[i] = h;
    lo[i] = __float2bfloat16(v - __bfloat162float(h));
}

// ---------------- bf16-split tensor GEMM: C = A@B^T (+bias) ----------------
__global__ __launch_bounds__(256) void tgemm_k(
    const __nv_bfloat16* __restrict__ AH0, const __nv_bfloat16* __restrict__ AL0,
    const __nv_bfloat16* __restrict__ AH1, const __nv_bfloat16* __restrict__ AL1,
    const __nv_bfloat16* __restrict__ BH0, const __nv_bfloat16* __restrict__ BL0,
    const __nv_bfloat16* __restrict__ BH1, const __nv_bfloat16* __restrict__ BL1,
    const float* __restrict__ bias0, const float* __restrict__ bias1,
    float* __restrict__ C0, float* __restrict__ C1,
    int ldc, int M, int K)
{
    __shared__ __nv_bfloat16 sA[2][128][40];
    __shared__ __nv_bfloat16 sB[2][128][40];
    int tid = threadIdx.x, w = tid >> 5, ln = tid & 31;
    int z = blockIdx.z;
    const __nv_bfloat16* AH = z ? AH1 : AH0;
    const __nv_bfloat16* AL = z ? AL1 : AL0;
    const __nv_bfloat16* BH = z ? BH1 : BH0;
    const __nv_bfloat16* BL = z ? BL1 : BL0;
    const float* bias = z ? bias1 : bias0;
    float* C = z ? C1 : C0;
    int m0 = blockIdx.y*128, n0 = blockIdx.x*128;
    int mw = (w >> 2)*64, nw = (w & 3)*32;

    float acc[4][4][4];
#pragma unroll
    for (int a = 0; a < 4; a++)
#pragma unroll
        for (int b = 0; b < 4; b++)
#pragma unroll
            for (int c = 0; c < 4; c++) acc[a][b][c] = 0.f;

    uint32_t sa0 = smem_u32(&sA[0][0][0]), sa1 = smem_u32(&sA[1][0][0]);
    uint32_t sb0 = smem_u32(&sB[0][0][0]), sb1 = smem_u32(&sB[1][0][0]);
    int g = ln >> 3, lr = ln & 7;
    int aRow = (g & 1)*8 + lr, aK = (g >> 1)*8;
    int bRow = (g >> 1)*8 + lr, bK = (g & 1)*8;

    for (int k0 = 0; k0 < K; k0 += 32) {
        for (int i = tid; i < 2048; i += 256) {
            int pl = i >> 9, r = (i >> 2) & 127, u = i & 3;
            uint4 v = make_uint4(0u,0u,0u,0u);
            if (pl < 2) {
                int gm = m0 + r;
                if (gm < M) v = *(const uint4*)((pl ? AL : AH) + (size_t)gm*K + k0 + u*8);
                *(uint4*)&sA[pl][r][u*8] = v;
            } else {
                v = *(const uint4*)(((pl & 1) ? BL : BH) + (size_t)(n0 + r)*K + k0 + u*8);
                *(uint4*)&sB[pl & 1][r][u*8] = v;
            }
        }
        __syncthreads();
#pragma unroll
        for (int kk = 0; kk < 32; kk += 16) {
            uint32_t ah[4][4], al[4][4], bh[2][4], bl[2][4];
#pragma unroll
            for (int mt = 0; mt < 4; mt++) {
                uint32_t off = (uint32_t)(((mw + mt*16 + aRow)*40 + kk + aK)*2);
                ldsm4(ah[mt][0], ah[mt][1], ah[mt][2], ah[mt][3], sa0 + off);
                ldsm4(al[mt][0], al[mt][1], al[mt][2], al[mt][3], sa1 + off);
            }
#pragma unroll
            for (int np = 0; np < 2; np++) {
                uint32_t off = (uint32_t)(((nw + np*16 + bRow)*40 + kk + bK)*2);
                ldsm4(bh[np][0], bh[np][1], bh[np][2], bh[np][3], sb0 + off);
                ldsm4(bl[np][0], bl[np][1], bl[np][2], bl[np][3], sb1 + off);
            }
#pragma unroll
            for (int mt = 0; mt < 4; mt++)
#pragma unroll
                for (int nt = 0; nt < 4; nt++) {
                    int np = nt >> 1, half = (nt & 1)*2;
                    mma16816(acc[mt][nt], ah[mt], bh[np][half], bh[np][half+1]);
                    mma16816(acc[mt][nt], ah[mt], bl[np][half], bl[np][half+1]);
                    mma16816(acc[mt][nt], al[mt], bh[np][half], bh[np][half+1]);
                }
        }
        __syncthreads();
    }
    int cr = ln >> 2, cc = (ln & 3)*2;
#pragma unroll
    for (int mt = 0; mt < 4; mt++) {
#pragma unroll
        for (int nt = 0; nt < 4; nt++) {
            int row = m0 + mw + mt*16 + cr;
            int col = n0 + nw + nt*8 + cc;
            float b0 = bias ? bias[col] : 0.f, b1 = bias ? bias[col+1] : 0.f;
            if (row < M) {
                float2 o; o.x = acc[mt][nt][0] + b0; o.y = acc[mt][nt][1] + b1;
                *(float2*)(C + (size_t)row*ldc + col) = o;
            }
            if (row + 8 < M) {
                float2 o; o.x = acc[mt][nt][2] + b0; o.y = acc[mt][nt][3] + b1;
                *(float2*)(C + (size_t)(row+8)*ldc + col) = o;
            }
        }
    }
}

// ---------------- small fp32 SGEMM (prenet / giU only) ----------------
__global__ __launch_bounds__(256) void sgemm_k(
    const float* __restrict__ A, int lda, const float* __restrict__ W, int ldw,
    const float* __restrict__ bias, float* __restrict__ C, int ldc,
    int M, int K, int act)
{
    __shared__ float As[16][132];
    __shared__ float Bs[16][68];
    int tid = threadIdx.x;
    int m0 = blockIdx.y*128, n0 = blockIdx.x*64;
    int tn = tid & 15, tmi = tid >> 4;
    float acc[8][4];
#pragma unroll
    for (int i = 0; i < 8; i++)
#pragma unroll
        for (int j = 0; j < 4; j++) acc[i][j] = 0.f;
    for (int k0 = 0; k0 < K; k0 += 16) {
#pragma unroll
        for (int l = 0; l < 2; l++) {
            int idx = tid + l*256;
            int m = idx >> 2, kq = (idx & 3)*4;
            float4 v = make_float4(0.f,0.f,0.f,0.f);
            if (m0 + m < M) v = *(const float4*)(A + (size_t)(m0+m)*lda + k0 + kq);
            As[kq][m]=v.x; As[kq+1][m]=v.y; As[kq+2][m]=v.z; As[kq+3][m]=v.w;
        }
        {
            int n = tid >> 2, kq = (tid & 3)*4;
            float4 v = *(const float4*)(W + (size_t)(n0+n)*ldw + k0 + kq);
            Bs[kq][n]=v.x; Bs[kq+1][n]=v.y; Bs[kq+2][n]=v.z; Bs[kq+3][n]=v.w;
        }
        __syncthreads();
#pragma unroll
        for (int k = 0; k < 16; k++) {
            float a[8], bb[4];
#pragma unroll
            for (int i = 0; i < 8; i++) a[i] = As[k][tmi*8+i];
#pragma unroll
            for (int j = 0; j < 4; j++) bb[j] = Bs[k][tn*4+j];
#pragma unroll
            for (int i = 0; i < 8; i++)
#pragma unroll
                for (int j = 0; j < 4; j++) acc[i][j] += a[i]*bb[j];
        }
        __syncthreads();
    }
    float bv[4] = {0.f,0.f,0.f,0.f};
    if (bias) {
#pragma unroll
        for (int j = 0; j < 4; j++) bv[j] = bias[n0 + tn*4 + j];
    }
#pragma unroll
    for (int i = 0; i < 8; i++) {
        int gm = m0 + tmi*8 + i;
        if (gm < M) {
            float4 o;
            o.x = acc[i][0]+bv[0]; o.y = acc[i][1]+bv[1];
            o.z = acc[i][2]+bv[2]; o.w = acc[i][3]+bv[3];
            if (act) { o.x=tanhf(o.x); o.y=tanhf(o.y); o.z=tanhf(o.z); o.w=tanhf(o.w); }
            *(float4*)(C + (size_t)gm*ldc + n0 + tn*4) = o;
        }
    }
}

// ---------------- encoder gate, step s, both dirs ----------------
__global__ void enc_gate_k(int s, const int* __restrict__ note) {
    int idx = blockIdx.x*256 + threadIdx.x;   // t*512+j
    int dir = blockIdx.z;
    int t = idx >> 9, j = idx & 511;
    int b = dir ? 31 - s : s;
    const float* giU = dir ? d_giUb : d_giUf;
    const float* gh  = dir ? d_ghB  : d_ghF;
    float* st        = dir ? d_stB  : d_stF;
    __nv_bfloat16* sh = dir ? d_stBH : d_stFH;
    __nv_bfloat16* sl = dir ? d_stBL : d_stFL;
    int nid = note[b*800 + t] & 127;
    const float* gi = giU + (size_t)nid*1536;
    const float* g  = gh + (size_t)t*1536;
    float ir = gi[j], iz = gi[512+j], in = gi[1024+j];
    float hr = g[j],  hz = g[512+j],  hn = g[1024+j];
    float h  = st[t*512 + j];
    float r = SIGM(ir+hr), z = SIGM(iz+hz);
    float nn = tanhf(in + r*hn);
    float hnew = (1.f - z)*nn + z*h;
    st[t*512 + j] = hnew;
    __nv_bfloat16 hb = __float2bfloat16(hnew);
    __nv_bfloat16 lb = __float2bfloat16(hnew - __bfloat162float(hb));
    sh[t*512 + j] = hb; sl[t*512 + j] = lb;
    size_t eo = ((size_t)t*32 + b)*1024 + dir*512 + j;
    d_encH[eo] = hb; d_encL[eo] = lb;
}

// ---------------- fold 64-dim prev embedding into dec gi ----------------
__global__ void uv_k(const float* __restrict__ fWih, const float* __restrict__ fW,
                     const float* __restrict__ fb,   const float* __restrict__ fbih,
                     const float* __restrict__ rWih, const float* __restrict__ rW,
                     const float* __restrict__ rb,   const float* __restrict__ rbih) {
    int i = blockIdx.x*256 + threadIdx.x;
    if (i >= 3072) return;
    int dec = i / 1536, j = i % 1536;
    const float* row = (dec ? rWih : fWih) + (size_t)j*1088 + 1024;
    const float* ew = dec ? rW : fW;
    const float* eb = dec ? rb : fb;
    float u = 0.f, v = 0.f;
#pragma unroll 8
    for (int c = 0; c < 64; c++) { u += ew[c]*row[c]; v += eb[c]*row[c]; }
    v += (dec ? rbih : fbih)[j];
    if (dec) { d_ur[j] = u; d_vr[j] = v; } else { d_uf[j] = u; d_vf[j] = v; }
}

// ---------------- persistent dual-decoder, 800 steps, tensor-core gh --------
// 128 blocks, 1/SM. Block = (dec = bb>>6, kb = (bb&63)*8).
// Barrier: R12's one-hop protocol (every block atomicAdd + direct poll) but
// with one counter PER DECODER (64 arrivals/64 pollers per line, lines 128B
// apart) — halves same-line contention, decouples the two decoders' skew.
__global__ __launch_bounds__(256, 1) void dec_k(
    const float* __restrict__ fbhh, const float* __restrict__ rbhh,
    const float* __restrict__ f0p,  const float* __restrict__ rmp)
{
    extern __shared__ char smc[];
    __nv_bfloat16* Whi = (__nv_bfloat16*)smc;     // [32][520]
    __nv_bfloat16* Wlo = Whi + 32*520;
    __nv_bfloat16* hHi = Wlo + 32*520;
    __nv_bfloat16* hLo = hHi + 32*520;
    float* ghs = (float*)(hLo + 32*520);          // [2][24][33]
    float* cb  = ghs + 2*24*33;                   // [72]

    int tid = threadIdx.x, bb = blockIdx.x;
    int w = tid >> 5, ln = tid & 31;
    int dec = bb >> 6, kb = (bb & 63)*8;
    const float* bhh = dec ? rbhh : fbhh;
    const float* gi  = dec ? d_gdr : d_gdf;
    const float* prv = dec ? rmp  : f0p;
    const __nv_bfloat16* WH = dec ? d_WhrH : d_WhfH;
    const __nv_bfloat16* WL = dec ? d_WhrL : d_WhfL;
    unsigned* histHL = d_histHL + (size_t)dec*(801*16384ll);
    float*    histF  = d_histF  + (size_t)dec*(801*16384ll);
    unsigned* cnt = &g_cnt2[dec*32];

    for (int i = tid; i < 1536; i += 256) {
        int row = i >> 6, c8 = i & 63;
        int j = (row >> 3)*512 + kb + (row & 7);
        *(uint4*)(Whi + row*520 + c8*8) = ((const uint4*)(WH + (size_t)j*512))[c8];
        *(uint4*)(Wlo + row*520 + c8*8) = ((const uint4*)(WL + (size_t)j*512))[c8];
    }
    for (int i = tid; i < 520; i += 256) {
        int row = 24 + i/65, c8 = i%65;
        *(uint4*)(Whi + row*520 + c8*8) = make_uint4(0,0,0,0);
        *(uint4*)(Wlo + row*520 + c8*8) = make_uint4(0,0,0,0);
    }
    if (tid < 24) {
        int jj = (tid >> 3)*512 + kb + (tid & 7);
        cb[tid]    = bhh[jj];
        cb[24+tid] = (dec ? d_ur : d_uf)[jj];
        cb[48+tid] = (dec ? d_vr : d_vf)[jj];
    }
    __syncthreads();

    uint32_t sWhi = smem_u32(Whi), sWlo = smem_u32(Wlo);
    uint32_t sHhi = smem_u32(hHi), sHlo = smem_u32(hLo);

    int mt = w & 1, np = (w >> 1) & 1, ks = w >> 2;
    int g = ln >> 3, lr = ln & 7;
    int aRow = (g & 1)*8 + lr, aK = (g >> 1)*8;
    int l4 = ln & 15;
    int bR = l4 & 7, bT = (l4 >> 3)*8;

    int gb = tid >> 3, gj = tid & 7;       // gate-phase (b, j)
    float b0c = cb[gj],    b1c = cb[8+gj],  b2c = cb[16+gj];
    float u0  = cb[24+gj], u1  = cb[32+gj], u2  = cb[40+gj];
    float v0  = cb[48+gj], v1  = cb[56+gj], v2  = cb[64+gj];
    float hold = 0.f;
    const float* prow = prv + gb*800;

    for (int t = 0; t < 800; t++) {
        size_t gbase = ((size_t)t*32 + gb)*1536 + kb + gj;
        float gir = gi[gbase], giz = gi[gbase+512], gin = gi[gbase+1024];
        float f = prow[t];
        const uint4* src = (const uint4*)(histHL + (size_t)t*16384);
        for (int i = tid; i < 4096; i += 256) {
            uint4 v = src[i];
            int b = i >> 7, j4 = (i & 127)*4;
            uint32_t h01 = (v.x & 0xffffu) | (v.y << 16);
            uint32_t h23 = (v.z & 0xffffu) | (v.w << 16);
            uint32_t l01 = (v.x >> 16) | (v.y & 0xffff0000u);
            uint32_t l23 = (v.z >> 16) | (v.w & 0xffff0000u);
            *(uint2*)(hHi + b*520 + j4) = make_uint2(h01, h23);
            *(uint2*)(hLo + b*520 + j4) = make_uint2(l01, l23);
        }
        __syncthreads();
        float c0[4] = {0.f,0.f,0.f,0.f}, c1[4] = {0.f,0.f,0.f,0.f};
#pragma unroll 4
        for (int k = 0; k < 16; k++) {
            int kk = (ks*16 + k)*16;
            uint32_t offA = (uint32_t)(((mt*16 + aRow)*520 + kk + aK)*2);
            uint32_t ah[4], al[4];
            ldsm4(ah[0],ah[1],ah[2],ah[3], sWhi + offA);
            ldsm4(al[0],al[1],al[2],al[3], sWlo + offA);
#pragma unroll
            for (int i2 = 0; i2 < 2; i2++) {
                int nbase = np*16 + i2*8;
                uint32_t offB = (uint32_t)(((nbase + bR)*520 + kk + bT)*2);
                uint32_t bh0,bh1,bl0,bl1;
                ldsm2(bh0,bh1, sHhi + offB);
                ldsm2(bl0,bl1, sHlo + offB);
                float* cc = i2 ? c1 : c0;
                mma16816(cc, ah, bh0, bh1);
                mma16816(cc, ah, bl0, bl1);
                mma16816(cc, al, bh0, bh1);
            }
        }
        {
            int row = mt*16 + (ln >> 2);
            int col = 2*(ln & 3);
            float* g0 = ghs + ks*(24*33);
#pragma unroll
            for (int i2 = 0; i2 < 2; i2++) {
                float* cc = i2 ? c1 : c0;
                int bcol = np*16 + i2*8 + col;
                g0[row*33 + bcol]     = cc[0];
                g0[row*33 + bcol + 1] = cc[1];
                if (mt == 0) {
                    g0[(row+8)*33 + bcol]     = cc[2];
                    g0[(row+8)*33 + bcol + 1] = cc[3];
                }
            }
        }
        __syncthreads();
        {
            float a0 = ghs[gj*33 + gb]      + ghs[24*33 + gj*33 + gb];
            float a1 = ghs[(8+gj)*33 + gb]  + ghs[24*33 + (8+gj)*33 + gb];
            float a2 = ghs[(16+gj)*33 + gb] + ghs[24*33 + (16+gj)*33 + gb];
            float ir = gir + f*u0 + v0;
            float iz = giz + f*u1 + v1;
            float in = gin + f*u2 + v2;
            float r = SIGM(ir + a0 + b0c);
            float z = SIGM(iz + a1 + b1c);
            float nn = tanhf(in + r*(a2 + b2c));
            float hnew = (1.f - z)*nn + z*hold;
            hold = hnew;
            __nv_bfloat16 hb = __float2bfloat16(hnew);
            __nv_bfloat16 lb = __float2bfloat16(hnew - __bfloat162float(hb));
            unsigned hu = *(unsigned short*)&hb;
            unsigned lu = *(unsigned short*)&lb;
            size_t o = (size_t)(t+1)*16384 + gb*512 + kb + gj;
            histHL[o] = hu | (lu << 16);
            histF[o]  = hnew;
        }
        if (t < 799) {
            __syncthreads();
            if (tid == 0) {
                __threadfence();
                atomicAdd(cnt, 1u);
                unsigned target = 64u*(unsigned)(t+1);
                while (*(volatile unsigned*)cnt < target) __nanosleep(32);
                __threadfence();
            }
            __syncthreads();
        }
    }
}

// ---------------- output projections ----------------
__global__ void out_k(const float* __restrict__ pfW, const float* __restrict__ pfb,
                      const float* __restrict__ prW, const float* __restrict__ prb,
                      float* __restrict__ out) {
    int t = blockIdx.x, dec = blockIdx.y, tid = threadIdx.x;
    int b = tid >> 3, seg = tid & 7;
    const float* W = dec ? prW : pfW;
    const float* h = d_histF + (size_t)dec*(801*16384ll) + (size_t)(t+1)*16384 + b*512 + seg*64;
    const float* Wp = W + seg*64;
    float s = 0.f;
#pragma unroll
    for (int jj = 0; jj < 64; jj += 4) {
        float4 hv = *(const float4*)(h + jj);
        float4 wv = *(const float4*)(Wp + jj);
        s += hv.x*wv.x + hv.y*wv.y + hv.z*wv.z + hv.w*wv.w;
    }
    s += __shfl_down_sync(0xffffffffu, s, 4);
    s += __shfl_down_sync(0xffffffffu, s, 2);
    s += __shfl_down_sync(0xffffffffu, s, 1);
    if (seg == 0) out[(size_t)dec*25600 + b*800 + t] = s + (dec ? prb[0] : pfb[0]);
}

// ---------------- host ----------------
extern "C" void kernel_launch(void* const* d_in, const int* in_sizes, int n_in,
                              void* d_out, int out_size) {
    const int*   note = (const int*)d_in[0];
    const float* f0p  = (const float*)d_in[1];
    const float* rmp  = (const float*)d_in[2];
    const float* nemb = (const float*)d_in[3];
    const float* f0W  = (const float*)d_in[4];
    const float* f0b  = (const float*)d_in[5];
    const float* rmW  = (const float*)d_in[6];
    const float* rmb  = (const float*)d_in[7];
    const float* p1W  = (const float*)d_in[8];
    const float* p1b  = (const float*)d_in[9];
    const float* p2W  = (const float*)d_in[10];
    const float* p2b  = (const float*)d_in[11];
    const float* efWih = (const float*)d_in[12];
    const float* efWhh = (const float*)d_in[13];
    const float* efbih = (const float*)d_in[14];
    const float* efbhh = (const float*)d_in[15];
    const float* ebWih = (const float*)d_in[16];
    const float* ebWhh = (const float*)d_in[17];
    const float* ebbih = (const float*)d_in[18];
    const float* ebbhh = (const float*)d_in[19];
    const float* dfWih = (const float*)d_in[20];
    const float* dfWhh = (const float*)d_in[21];
    const float* dfbih = (const float*)d_in[22];
    const float* dfbhh = (const float*)d_in[23];
    const float* drWih = (const float*)d_in[24];
    const float* drWhh = (const float*)d_in[25];
    const float* drbih = (const float*)d_in[26];
    const float* drbhh = (const float*)d_in[27];
    const float* pfW   = (const float*)d_in[28];
    const float* pfb   = (const float*)d_in[29];
    const float* prW   = (const float*)d_in[30];
    const float* prb   = (const float*)d_in[31];

    float *hU1, *hU, *giUf, *giUb, *stF, *stB, *ghF, *ghB, *gdf, *gdr;
    __nv_bfloat16 *WefH,*WefL,*WebH,*WebL,*WdfH,*WdfL,*WdrH,*WdrL;
    __nv_bfloat16 *WhfH,*WhfL,*WhrH,*WhrL;
    __nv_bfloat16 *stFH,*stFL,*stBH,*stBL,*encH,*encL;
    cudaGetSymbolAddress((void**)&hU1,  d_hU1);
    cudaGetSymbolAddress((void**)&hU,   d_hU);
    cudaGetSymbolAddress((void**)&giUf, d_giUf);
    cudaGetSymbolAddress((void**)&giUb, d_giUb);
    cudaGetSymbolAddress((void**)&stF,  d_stF);
    cudaGetSymbolAddress((void**)&stB,  d_stB);
    cudaGetSymbolAddress((void**)&ghF,  d_ghF);
    cudaGetSymbolAddress((void**)&ghB,  d_ghB);
    cudaGetSymbolAddress((void**)&gdf,  d_gdf);
    cudaGetSymbolAddress((void**)&gdr,  d_gdr);
    cudaGetSymbolAddress((void**)&WefH, d_WefH); cudaGetSymbolAddress((void**)&WefL, d_WefL);
    cudaGetSymbolAddress((void**)&WebH, d_WebH); cudaGetSymbolAddress((void**)&WebL, d_WebL);
    cudaGetSymbolAddress((void**)&WdfH, d_WdfH); cudaGetSymbolAddress((void**)&WdfL, d_WdfL);
    cudaGetSymbolAddress((void**)&WdrH, d_WdrH); cudaGetSymbolAddress((void**)&WdrL, d_WdrL);
    cudaGetSymbolAddress((void**)&WhfH, d_WhfH); cudaGetSymbolAddress((void**)&WhfL, d_WhfL);
    cudaGetSymbolAddress((void**)&WhrH, d_WhrH); cudaGetSymbolAddress((void**)&WhrL, d_WhrL);
    cudaGetSymbolAddress((void**)&stFH, d_stFH); cudaGetSymbolAddress((void**)&stFL, d_stFL);
    cudaGetSymbolAddress((void**)&stBH, d_stBH); cudaGetSymbolAddress((void**)&stBL, d_stBL);
    cudaGetSymbolAddress((void**)&encH, d_encH); cudaGetSymbolAddress((void**)&encL, d_encL);

    init_k<<<1600, 256>>>();

    // weight hi/lo conversions
    cvt_k<<<3072, 256>>>(efWhh, 512, 512, WefH, WefL, 786432);
    cvt_k<<<3072, 256>>>(ebWhh, 512, 512, WebH, WebL, 786432);
    cvt_k<<<6144, 256>>>(dfWih, 1088, 1024, WdfH, WdfL, 1572864);
    cvt_k<<<6144, 256>>>(drWih, 1088, 1024, WdrH, WdrL, 1572864);
    cvt_k<<<3072, 256>>>(dfWhh, 512, 512, WhfH, WhfL, 786432);
    cvt_k<<<3072, 256>>>(drWhh, 512, 512, WhrH, WhrL, 786432);

    // prenet + encoder input projections on 128 unique notes (fp32)
    sgemm_k<<<dim3(4,1), 256>>>(nemb, 256, p1W, 256, p1b, hU1, 256, 128, 256, 1);
    sgemm_k<<<dim3(4,1), 256>>>(hU1, 256, p2W, 256, p2b, hU,  256, 128, 256, 1);
    sgemm_k<<<dim3(24,1), 256>>>(hU, 256, efWih, 256, efbih, giUf, 1536, 128, 256, 0);
    sgemm_k<<<dim3(24,1), 256>>>(hU, 256, ebWih, 256, ebbih, giUb, 1536, 128, 256, 0);
    uv_k<<<12, 256>>>(dfWih, f0W, f0b, dfbih, drWih, rmW, rmb, drbih);

    // encoder recurrence over B=32 steps (tensor, both dirs fused)
    for (int s = 0; s < 32; s++) {
        tgemm_k<<<dim3(12,7,2), 256>>>(
            stFH, stFL, stBH, stBL,
            WefH, WefL, WebH, WebL,
            efbhh, ebbhh, ghF, ghB, 1536, 800, 512);
        enc_gate_k<<<dim3(1600,1,2), 256>>>(s, note);
    }

    // decoder input projections (tensor, both decs fused)
    tgemm_k<<<dim3(12,200,2), 256>>>(
        encH, encL, encH, encL,
        WdfH, WdfL, WdrH, WdrL,
        nullptr, nullptr, gdf, gdr, 1536, 25600, 1024);

    // persistent dual decoder (tensor-core recurrence)
    int smem = 4*(32*520)*2 + (2*24*33 + 72)*4;   // 139744 B
    cudaFuncSetAttribute(dec_k, cudaFuncAttributeMaxDynamicSharedMemorySize, smem);
    dec_k<<<128, 256, smem>>>(dfbhh, drbhh, f0p, rmp);

    out_k<<<dim3(800,2), 256>>>(pfW, pfb, prW, prb, (float*)d_out);
}